// round 8
// baseline (speedup 1.0000x reference)
#include <cuda_runtime.h>

// =====================================================================
// Sparse-emulated 3D CNN: scatter -> 14 masked 3x3x3 convs + 6 maxpools
// Dense fp32. Large layers (D>=16): tiled f32x2-FMA kernel (FFMA2),
// float4-vectorized smem fills, hoisted halo addressing, I$-bounded loops.
// Small layers (D<=8): one-block-per-voxel kernel, halo fully in smem,
// runtime tap bounds, 4-way accumulator ILP. Pools: float4-vectorized.
// =====================================================================

using ull = unsigned long long;

#define GRID0 64
#define NVOX  262144  // 64^3

// Scratch (allocation-free: __device__ globals). Two ping-pong activation
// buffers sized for the largest activation (64^3 x 64ch = 67MB each).
__device__ __align__(128) float g_bufA[NVOX * 64];
__device__ __align__(128) float g_bufB[NVOX * 64];
// Masks for all 7 resolutions packed into one array.
__device__ __align__(128) float g_mask[262144 + 32768 + 4096 + 512 + 64 + 8 + 1 + 7];
__device__ int g_win[NVOX];

// ---------------- packed f32x2 helpers ----------------
__device__ __forceinline__ ull fma2(ull a, ull b, ull c) {
    ull d;
    asm("fma.rn.f32x2 %0, %1, %2, %3;" : "=l"(d) : "l"(a), "l"(b), "l"(c));
    return d;
}
__device__ __forceinline__ ull dup2(float v) {
    ull d;
    asm("mov.b64 %0, {%1, %1};" : "=l"(d) : "f"(v));
    return d;
}
__device__ __forceinline__ float2 unpack2(ull v) {
    float2 f;
    asm("mov.b64 {%0, %1}, %2;" : "=f"(f.x), "=f"(f.y) : "l"(v));
    return f;
}

// ---------------- init + scatter (last-write-wins) ----------------
__global__ void k_init() {
    int v = blockIdx.x * 256 + threadIdx.x;
    if (v < NVOX) {
        g_win[v] = -1;
        g_mask[v] = 0.f;
        g_bufA[v * 3 + 0] = 0.f;
        g_bufA[v * 3 + 1] = 0.f;
        g_bufA[v * 3 + 2] = 0.f;
    }
}

__global__ void k_scatter_max(const int* __restrict__ coors, int n) {
    int i = blockIdx.x * 256 + threadIdx.x;
    if (i < n) {
        int z = coors[3 * i + 0], y = coors[3 * i + 1], x = coors[3 * i + 2];
        atomicMax(&g_win[(z * GRID0 + y) * GRID0 + x], i);
    }
}

__global__ void k_scatter_write(const float* __restrict__ feats) {
    int v = blockIdx.x * 256 + threadIdx.x;
    if (v < NVOX) {
        int w = g_win[v];
        if (w >= 0) {
            g_bufA[v * 3 + 0] = feats[3 * w + 0];
            g_bufA[v * 3 + 1] = feats[3 * w + 1];
            g_bufA[v * 3 + 2] = feats[3 * w + 2];
            g_mask[v] = 1.f;
        }
    }
}

// ---------------- large-D conv: 3x3x3 SAME, output masked ----------------
// Block computes a 4(z) x 4(y) x 8(x) voxel tile x 32 output channels.
// 128 threads: tc = tid&3 -> 8 couts each (4 f32x2 pairs); tv = tid>>2 ->
// (vy = tv>>3, vx = tv&7); 4 voxels along z per thread.
// Inputs stored duplicated ({v,v}) in smem so one LDS.64 feeds f32x2 FMAs;
// weights read as 2x ulonglong2 (4 cout-pairs). Channel chunk KC=4.
// Halo gmem addressing hoisted out of the chunk loop (loop-invariant).
template <int CIN, int COUT>
__global__ void __launch_bounds__(128) k_conv(const float* __restrict__ in,
                                              const float* __restrict__ W,
                                              float* __restrict__ out,
                                              const float* __restrict__ mask,
                                              int D) {
    constexpr int KC  = (CIN % 4 == 0) ? 4 : CIN;  // 4, or 3 for the first layer
    constexpr int NCH = CIN / KC;
    constexpr int STR = KC + 1;                    // pad to dodge bank conflicts
    constexpr int NCT = COUT / 32;
    constexpr int HV  = 6 * 6 * 10;                // 6x6x10 halo voxels = 360

    __shared__ ull sIn[HV * STR];                  // halo, dup pairs
    __shared__ __align__(16) float sW[27 * KC * 32];

    const int tilesX = (D + 7) >> 3;
    const int tilesY = (D + 3) >> 2;
    int bi = blockIdx.x;
    const int ct = bi % NCT;
    int tb = bi / NCT;
    const int tx = tb % tilesX; tb /= tilesX;
    const int ty = tb % tilesY;
    const int tz = tb / tilesY;
    const int z0 = tz * 4, y0 = ty * 4, x0 = tx * 8;
    const int c0 = ct * 32;

    const int tid = threadIdx.x;
    const int tc  = tid & 3;   // cout group: couts c0 + tc*8 .. +7
    const int tv  = tid >> 2;  // 0..31
    const int vy  = tv >> 3;   // 0..3
    const int vx  = tv & 7;    // 0..7

    // --- hoisted halo addressing: each thread owns <=3 halo voxels ---
    const float* hsrc[3];
    ull*         hdst[3];
#pragma unroll
    for (int s = 0; s < 3; s++) {
        int v = tid + s * 128;
        hsrc[s] = nullptr;
        hdst[s] = nullptr;
        if (v < HV) {
            int lz = v / 60, r = v - lz * 60;
            int ly = r / 10, lx = r - ly * 10;
            int gz = z0 - 1 + lz, gy = y0 - 1 + ly, gx = x0 - 1 + lx;
            hdst[s] = &sIn[v * STR];
            if ((unsigned)gz < (unsigned)D && (unsigned)gy < (unsigned)D &&
                (unsigned)gx < (unsigned)D)
                hsrc[s] = &in[((gz * D + gy) * D + gx) * CIN];
        }
    }

    ull acc[4][4];
#pragma unroll
    for (int i = 0; i < 4; i++)
#pragma unroll
        for (int j = 0; j < 4; j++) acc[i][j] = 0ull;

#pragma unroll 1
    for (int ch = 0; ch < NCH; ch++) {
        const int ck = ch * KC;

        // --- load input halo chunk ---
        if (KC == 4) {
#pragma unroll
            for (int s = 0; s < 3; s++) {
                if (hdst[s]) {
                    float4 val = make_float4(0.f, 0.f, 0.f, 0.f);
                    if (hsrc[s]) val = *(const float4*)(hsrc[s] + ck);
                    ull* sp = hdst[s];
                    sp[0] = dup2(val.x);
                    sp[1] = dup2(val.y);
                    sp[2] = dup2(val.z);
                    sp[3] = dup2(val.w);
                }
            }
        } else {
            // Scalar path (layer 0, CIN=3 only).
            for (int i = tid; i < HV * KC; i += 128) {
                int v = i / KC, k = i - v * KC;
                int lz = v / 60, r = v - lz * 60;
                int ly = r / 10, lx = r - ly * 10;
                int gz = z0 - 1 + lz, gy = y0 - 1 + ly, gx = x0 - 1 + lx;
                float val = 0.f;
                if ((unsigned)gz < (unsigned)D && (unsigned)gy < (unsigned)D &&
                    (unsigned)gx < (unsigned)D)
                    val = in[((gz * D + gy) * D + gx) * CIN + ck + k];
                sIn[v * STR + k] = dup2(val);
            }
        }
        // --- load weight chunk: rows (t,k) x 32 couts, float4 both sides ---
        for (int i = tid; i < 27 * KC * 8; i += 128) {
            int row = i >> 3, c4 = i & 7;          // c = c4*4
            int t = row / KC, k = row - t * KC;
            *(float4*)&sW[row * 32 + c4 * 4] =
                *(const float4*)&W[(t * CIN + ck + k) * COUT + c0 + c4 * 4];
        }
        __syncthreads();

#pragma unroll 1
        for (int dz = 0; dz < 3; ++dz)
#pragma unroll
            for (int dy = 0; dy < 3; ++dy) {
                const int vb = dz * 60 + (vy + dy) * 10 + vx;
                const float* wrow = &sW[(dz * 3 + dy) * 3 * KC * 32 + (tc << 3)];
#pragma unroll
                for (int dx = 0; dx < 3; ++dx) {
                    const ull* ip = &sIn[(vb + dx) * STR];
                    const float* wp = wrow + dx * KC * 32;
#pragma unroll
                    for (int k = 0; k < KC; ++k) {
                        ulonglong2 wA = *(const ulonglong2*)(wp + k * 32);
                        ulonglong2 wB = *(const ulonglong2*)(wp + k * 32 + 4);
#pragma unroll
                        for (int vz = 0; vz < 4; ++vz) {
                            ull a = ip[vz * (60 * STR) + k];
                            acc[vz][0] = fma2(a, wA.x, acc[vz][0]);
                            acc[vz][1] = fma2(a, wA.y, acc[vz][1]);
                            acc[vz][2] = fma2(a, wB.x, acc[vz][2]);
                            acc[vz][3] = fma2(a, wB.y, acc[vz][3]);
                        }
                    }
                }
            }
        __syncthreads();
    }

    // --- epilogue: mask and store (2x float4 per voxel) ---
    const int cb = c0 + (tc << 3);
    const int gy = y0 + vy, gx = x0 + vx;
    if (gy < D && gx < D) {
#pragma unroll
        for (int vz = 0; vz < 4; ++vz) {
            int gz = z0 + vz;
            if (gz < D) {
                int vox = (gz * D + gy) * D + gx;
                float m = mask[vox];
                float4 o0, o1;
                if (m > 0.f) {
                    float2 p0 = unpack2(acc[vz][0]);
                    float2 p1 = unpack2(acc[vz][1]);
                    float2 p2 = unpack2(acc[vz][2]);
                    float2 p3 = unpack2(acc[vz][3]);
                    o0 = make_float4(p0.x, p0.y, p1.x, p1.y);
                    o1 = make_float4(p2.x, p2.y, p3.x, p3.y);
                } else {
                    o0 = make_float4(0.f, 0.f, 0.f, 0.f);
                    o1 = make_float4(0.f, 0.f, 0.f, 0.f);
                }
                float* op = out + (size_t)vox * COUT + cb;
                *(float4*)(op)     = o0;
                *(float4*)(op + 4) = o1;
            }
        }
    }
}

// ---------------- small-D conv (D<=8): one block per voxel ----------------
// Block = COUT threads (one cout each). Full 3x3x3 x CIN halo loaded into
// smem once (<= 27KB). Runtime tap bounds skip out-of-range taps entirely
// (at D=1 only the center tap runs). Weights streamed from L2 with
// coalesced LDG; 4 independent accumulators break the FMA RAW chain.
template <int CIN, int COUT>
__global__ void __launch_bounds__(256) k_conv_small(const float* __restrict__ in,
                                                    const float* __restrict__ W,
                                                    float* __restrict__ out,
                                                    const float* __restrict__ mask,
                                                    int D) {
    __shared__ __align__(16) float sIn[27 * CIN];

    const int vox = blockIdx.x;
    const int x = vox % D;
    const int t0 = vox / D;
    const int y = t0 % D;
    const int z = t0 / D;
    const int c = threadIdx.x;  // 0..COUT-1

    // Valid tap ranges (SAME padding): dz such that z+dz-1 in [0, D).
    const int dz0 = (z > 0) ? 0 : 1, dz1 = (z < D - 1) ? 2 : 1;
    const int dy0 = (y > 0) ? 0 : 1, dy1 = (y < D - 1) ? 2 : 1;
    const int dx0 = (x > 0) ? 0 : 1, dx1 = (x < D - 1) ? 2 : 1;

    // Cooperative halo load of the valid taps only (flat over valid range).
    const int nz = dz1 - dz0 + 1, ny = dy1 - dy0 + 1, nx = dx1 - dx0 + 1;
    const int nv = nz * ny * nx;
    for (int i = c; i < nv * CIN; i += COUT) {
        int v = i / CIN, k = i - v * CIN;
        int lz = v / (ny * nx), r = v - lz * (ny * nx);
        int ly = r / nx, lx = r - ly * nx;
        int dz = dz0 + lz, dy = dy0 + ly, dx = dx0 + lx;
        int gz = z + dz - 1, gy = y + dy - 1, gx = x + dx - 1;
        sIn[((dz * 3 + dy) * 3 + dx) * CIN + k] =
            in[((gz * D + gy) * D + gx) * CIN + k];
    }
    __syncthreads();

    float a0 = 0.f, a1 = 0.f, a2 = 0.f, a3 = 0.f;
#pragma unroll 1
    for (int dz = dz0; dz <= dz1; ++dz)
#pragma unroll 1
        for (int dy = dy0; dy <= dy1; ++dy)
#pragma unroll 1
            for (int dx = dx0; dx <= dx1; ++dx) {
                const int tap = (dz * 3 + dy) * 3 + dx;
                const float* ip = &sIn[tap * CIN];
                const float* wp = &W[tap * CIN * COUT + c];
#pragma unroll 4
                for (int k = 0; k < CIN; k += 4) {
                    float4 a = *(const float4*)(ip + k);
                    a0 = fmaf(a.x, wp[(k + 0) * COUT], a0);
                    a1 = fmaf(a.y, wp[(k + 1) * COUT], a1);
                    a2 = fmaf(a.z, wp[(k + 2) * COUT], a2);
                    a3 = fmaf(a.w, wp[(k + 3) * COUT], a3);
                }
            }
    float acc = (a0 + a1) + (a2 + a3);

    float m = mask[vox];
    out[(size_t)vox * COUT + c] = (m > 0.f) ? acc : 0.f;
}

// ---------------- masked 2x2x2 max-pool (float4 per thread) ----------------
// One block per output voxel, C/4 threads; each thread reduces one
// channel-quad across the 8-voxel window with float4 loads.
__global__ void k_pool(const float* __restrict__ in, float* __restrict__ out,
                       const float* __restrict__ mIn, float* __restrict__ mOut,
                       int Do, int C) {
    int vo = blockIdx.x;
    int c4 = threadIdx.x;          // channel quad index, 0..C/4-1
    int xo = vo % Do; int t = vo / Do;
    int yo = t % Do;  int zo = t / Do;
    int D  = Do * 2;
    const float4* in4 = (const float4*)in;
    const int C4 = C >> 2;

    float m = 0.f;
    float4 val = make_float4(-3.402823466e+38f, -3.402823466e+38f,
                             -3.402823466e+38f, -3.402823466e+38f);
#pragma unroll
    for (int a = 0; a < 2; a++)
#pragma unroll
        for (int b = 0; b < 2; b++)
#pragma unroll
            for (int e = 0; e < 2; e++) {
                int vi = ((zo * 2 + a) * D + (yo * 2 + b)) * D + (xo * 2 + e);
                if (mIn[vi] > 0.f) {
                    m = 1.f;
                    float4 v = in4[(size_t)vi * C4 + c4];
                    val.x = fmaxf(val.x, v.x);
                    val.y = fmaxf(val.y, v.y);
                    val.z = fmaxf(val.z, v.z);
                    val.w = fmaxf(val.w, v.w);
                }
            }
    float4 o = (m > 0.f) ? val : make_float4(0.f, 0.f, 0.f, 0.f);
    ((float4*)out)[(size_t)vo * C4 + c4] = o;
    if (c4 == 0) mOut[vo] = m;
}

// ---------------- launch ----------------
static inline int convgrid(int D, int cout) {
    int tx = (D + 7) / 8;
    int ty = (D + 3) / 4;
    return tx * ty * ty * (cout / 32);
}

extern "C" void kernel_launch(void* const* d_in, const int* in_sizes, int n_in,
                              void* d_out, int out_size) {
    const float* feats = (const float*)d_in[0];
    const int*   coors = (const int*)d_in[1];
    const float* Wp[14];
    for (int i = 0; i < 14; i++) Wp[i] = (const float*)d_in[2 + i];
    const int N = in_sizes[0] / 3;

    float *bufA, *bufB, *maskBase;
    cudaGetSymbolAddress((void**)&bufA, g_bufA);
    cudaGetSymbolAddress((void**)&bufB, g_bufB);
    cudaGetSymbolAddress((void**)&maskBase, g_mask);
    const int moff[7] = {0, 262144, 294912, 299008, 299520, 299584, 299592};
    float* mk[7];
    for (int i = 0; i < 7; i++) mk[i] = maskBase + moff[i];

    k_init<<<NVOX / 256, 256>>>();
    k_scatter_max<<<(N + 255) / 256, 256>>>(coors, N);
    k_scatter_write<<<NVOX / 256, 256>>>(feats);

    // block 0 @ 64^3
    k_conv<3, 64><<<convgrid(64, 64), 128>>>(bufA, Wp[0], bufB, mk[0], 64);
    k_conv<64, 64><<<convgrid(64, 64), 128>>>(bufB, Wp[1], bufA, mk[0], 64);
    k_pool<<<32 * 32 * 32, 64 / 4>>>(bufA, bufB, mk[0], mk[1], 32, 64);
    // block 1 @ 32^3
    k_conv<64, 96><<<convgrid(32, 96), 128>>>(bufB, Wp[2], bufA, mk[1], 32);
    k_conv<96, 96><<<convgrid(32, 96), 128>>>(bufA, Wp[3], bufB, mk[1], 32);
    k_pool<<<16 * 16 * 16, 96 / 4>>>(bufB, bufA, mk[1], mk[2], 16, 96);
    // block 2 @ 16^3
    k_conv<96, 128><<<convgrid(16, 128), 128>>>(bufA, Wp[4], bufB, mk[2], 16);
    k_conv<128, 128><<<convgrid(16, 128), 128>>>(bufB, Wp[5], bufA, mk[2], 16);
    k_pool<<<8 * 8 * 8, 128 / 4>>>(bufA, bufB, mk[2], mk[3], 8, 128);
    // block 3 @ 8^3  (small-D path: one block per voxel)
    k_conv_small<128, 160><<<512, 160>>>(bufB, Wp[6], bufA, mk[3], 8);
    k_conv_small<160, 160><<<512, 160>>>(bufA, Wp[7], bufB, mk[3], 8);
    k_pool<<<4 * 4 * 4, 160 / 4>>>(bufB, bufA, mk[3], mk[4], 4, 160);
    // block 4 @ 4^3
    k_conv_small<160, 192><<<64, 192>>>(bufA, Wp[8], bufB, mk[4], 4);
    k_conv_small<192, 192><<<64, 192>>>(bufB, Wp[9], bufA, mk[4], 4);
    k_pool<<<2 * 2 * 2, 192 / 4>>>(bufA, bufB, mk[4], mk[5], 2, 192);
    // block 5 @ 2^3
    k_conv_small<192, 224><<<8, 224>>>(bufB, Wp[10], bufA, mk[5], 2);
    k_conv_small<224, 224><<<8, 224>>>(bufA, Wp[11], bufB, mk[5], 2);
    k_pool<<<1, 224 / 4>>>(bufB, bufA, mk[5], mk[6], 1, 224);
    // block 6 @ 1^3 -> final output (1,1,1,1,256)
    k_conv_small<224, 256><<<1, 256>>>(bufA, Wp[12], bufB, mk[6], 1);
    k_conv_small<256, 256><<<1, 256>>>(bufB, Wp[13], (float*)d_out, mk[6], 1);
}

// round 12
// speedup vs baseline: 1.1942x; 1.1942x over previous
#include <cuda_runtime.h>

// =====================================================================
// Sparse-emulated 3D CNN: scatter -> 14 masked 3x3x3 convs + 6 maxpools
// fp32. Layer1 (64^3, 64->64, 60% of MACs): GATHER conv over compacted
// occupied-voxel list (output sparsity: ~37% voxels occupied), padded
// input buffer -> constant tap offsets, sparse repack. Other large
// layers: dense tiled FFMA2 kernel. D<=8: per-voxel kernel. Pools: float4.
// =====================================================================

using ull = unsigned long long;

#define GRID0 64
#define NVOX  262144  // 64^3
#define PDIM  66
#define PSLAB (PDIM * PDIM)   // 4356

__device__ __align__(128) float g_bufA[NVOX * 64];
__device__ __align__(128) float g_bufB[NVOX * 64];
__device__ __align__(128) float g_pad[PDIM * PDIM * PDIM * 64];  // 66^3 x 64ch
__device__ __align__(128) float g_mask[262144 + 32768 + 4096 + 512 + 64 + 8 + 1 + 7];
__device__ int g_win[NVOX];
__device__ int g_list[NVOX];
__device__ int g_nocc;

// ---------------- packed f32x2 helpers ----------------
__device__ __forceinline__ ull fma2(ull a, ull b, ull c) {
    ull d;
    asm("fma.rn.f32x2 %0, %1, %2, %3;" : "=l"(d) : "l"(a), "l"(b), "l"(c));
    return d;
}
__device__ __forceinline__ ull dup2(float v) {
    ull d;
    asm("mov.b64 %0, {%1, %1};" : "=l"(d) : "f"(v));
    return d;
}
__device__ __forceinline__ float2 unpack2(ull v) {
    float2 f;
    asm("mov.b64 {%0, %1}, %2;" : "=f"(f.x), "=f"(f.y) : "l"(v));
    return f;
}

// ---------------- init + scatter (last-write-wins) + compact ----------------
__global__ void k_init() {
    int v = blockIdx.x * 256 + threadIdx.x;
    if (v < NVOX) {
        g_win[v] = -1;
        g_mask[v] = 0.f;
        g_bufA[v * 3 + 0] = 0.f;
        g_bufA[v * 3 + 1] = 0.f;
        g_bufA[v * 3 + 2] = 0.f;
    }
    if (v == 0) g_nocc = 0;
}

__global__ void k_scatter_max(const int* __restrict__ coors, int n) {
    int i = blockIdx.x * 256 + threadIdx.x;
    if (i < n) {
        int z = coors[3 * i + 0], y = coors[3 * i + 1], x = coors[3 * i + 2];
        atomicMax(&g_win[(z * GRID0 + y) * GRID0 + x], i);
    }
}

__global__ void k_scatter_write(const float* __restrict__ feats) {
    int v = blockIdx.x * 256 + threadIdx.x;
    if (v < NVOX) {
        int w = g_win[v];
        if (w >= 0) {
            g_bufA[v * 3 + 0] = feats[3 * w + 0];
            g_bufA[v * 3 + 1] = feats[3 * w + 1];
            g_bufA[v * 3 + 2] = feats[3 * w + 2];
            g_mask[v] = 1.f;
        }
    }
}

__global__ void k_compact() {
    int v = blockIdx.x * 256 + threadIdx.x;
    if (v < NVOX && g_mask[v] > 0.f) {
        int p = atomicAdd(&g_nocc, 1);
        g_list[p] = v;
    }
}

// Zero the padded buffer (66^3 x 64ch) every launch; repack only writes
// occupied voxels, so unoccupied interior + borders stay zero.
__global__ void k_zero() {
    const int NP4 = (PDIM * PDIM * PDIM * 64) / 4;   // 4,599,936
    int i = blockIdx.x * 256 + threadIdx.x;
    if (i < NP4) ((float4*)g_pad)[i] = make_float4(0.f, 0.f, 0.f, 0.f);
}

// Sparse repack: copy only mask>0 voxels (others are zero in bufB and
// pre-zeroed in pad) from dense 64^3 layout into padded 66^3 layout.
__global__ void k_repack() {
    int i = blockIdx.x * 256 + threadIdx.x;   // over NVOX*16 float4s
    if (i < NVOX * 16) {
        int v = i >> 4;
        if (g_mask[v] > 0.f) {
            int c4 = i & 15;
            int z = v >> 12, y = (v >> 6) & 63, x = v & 63;
            int pidx = ((z + 1) * PDIM + (y + 1)) * PDIM + (x + 1);
            ((float4*)g_pad)[(size_t)pidx * 16 + c4] = ((const float4*)g_bufB)[i];
        }
    }
}

// ---------------- gather conv (64^3 layer 1, CIN=COUT=64) ----------------
// Block: 64 occupied voxels x 64 couts. 128 threads: tc=tid&7 -> 8 couts,
// tv=tid>>3 -> 4 voxels each. Inputs via LDG.128 from padded buffer
// (constant tap offsets, no bounds checks); weights chunked in smem.
// Tap loop partially unrolled (x3) for load/compute software pipelining.
// Unoccupied voxels of `out` are never written; downstream pool only
// reads masked voxels, which is exactly the written set.
__global__ void __launch_bounds__(128) k_gconv(const float* __restrict__ pad,
                                               const float* __restrict__ W,
                                               float* __restrict__ out) {
    constexpr int CIN = 64, COUT = 64, KC = 4, NCH = CIN / KC;
    __shared__ __align__(16) float sW[27 * KC * COUT];  // 27.6KB

    const int nocc = g_nocc;
    const int base = blockIdx.x * 64;
    if (base >= nocc) return;

    const int tid = threadIdx.x;
    const int tc  = tid & 7;    // couts tc*8 .. +7
    const int tv  = tid >> 3;   // 0..15 -> voxels base + tv*4 + j

    const float* p[4];
    int vi[4];
#pragma unroll
    for (int j = 0; j < 4; j++) {
        int i = base + tv * 4 + j;
        vi[j] = (i < nocc) ? g_list[i] : -1;
        int v = (vi[j] >= 0) ? vi[j] : 0;
        int z = v >> 12, y = (v >> 6) & 63, x = v & 63;
        p[j] = pad + (size_t)(((z + 1) * PDIM + (y + 1)) * PDIM + (x + 1)) * CIN;
    }

    ull acc[4][4];
#pragma unroll
    for (int j = 0; j < 4; j++)
#pragma unroll
        for (int q = 0; q < 4; q++) acc[j][q] = 0ull;

#pragma unroll 1
    for (int ch = 0; ch < NCH; ch++) {
        const int ck = ch * KC;
        // weights: 27*KC rows x 64 couts, float4 both sides
        for (int i = tid; i < 27 * KC * 16; i += 128) {
            int row = i >> 4, c4 = i & 15;
            int t = row / KC, k = row - t * KC;
            *(float4*)&sW[row * COUT + c4 * 4] =
                *(const float4*)&W[(t * CIN + ck + k) * COUT + c4 * 4];
        }
        __syncthreads();

#pragma unroll 3
        for (int t = 0; t < 27; ++t) {
            int dz = t / 9, r = t - dz * 9;
            int dy = r / 3, dx = r - dy * 3;
            const int off = ((dz - 1) * PSLAB + (dy - 1) * PDIM + (dx - 1)) * CIN + ck;
            float4 a0 = *(const float4*)(p[0] + off);
            float4 a1 = *(const float4*)(p[1] + off);
            float4 a2 = *(const float4*)(p[2] + off);
            float4 a3 = *(const float4*)(p[3] + off);
            const float* wp = &sW[t * KC * COUT + tc * 8];
#pragma unroll
            for (int k = 0; k < KC; ++k) {
                ulonglong2 wA = *(const ulonglong2*)(wp + k * COUT);
                ulonglong2 wB = *(const ulonglong2*)(wp + k * COUT + 4);
                float e0 = (k == 0) ? a0.x : (k == 1) ? a0.y : (k == 2) ? a0.z : a0.w;
                float e1 = (k == 0) ? a1.x : (k == 1) ? a1.y : (k == 2) ? a1.z : a1.w;
                float e2 = (k == 0) ? a2.x : (k == 1) ? a2.y : (k == 2) ? a2.z : a2.w;
                float e3 = (k == 0) ? a3.x : (k == 1) ? a3.y : (k == 2) ? a3.z : a3.w;
                ull d0 = dup2(e0), d1 = dup2(e1), d2 = dup2(e2), d3 = dup2(e3);
                acc[0][0] = fma2(d0, wA.x, acc[0][0]);
                acc[0][1] = fma2(d0, wA.y, acc[0][1]);
                acc[0][2] = fma2(d0, wB.x, acc[0][2]);
                acc[0][3] = fma2(d0, wB.y, acc[0][3]);
                acc[1][0] = fma2(d1, wA.x, acc[1][0]);
                acc[1][1] = fma2(d1, wA.y, acc[1][1]);
                acc[1][2] = fma2(d1, wB.x, acc[1][2]);
                acc[1][3] = fma2(d1, wB.y, acc[1][3]);
                acc[2][0] = fma2(d2, wA.x, acc[2][0]);
                acc[2][1] = fma2(d2, wA.y, acc[2][1]);
                acc[2][2] = fma2(d2, wB.x, acc[2][2]);
                acc[2][3] = fma2(d2, wB.y, acc[2][3]);
                acc[3][0] = fma2(d3, wA.x, acc[3][0]);
                acc[3][1] = fma2(d3, wA.y, acc[3][1]);
                acc[3][2] = fma2(d3, wB.x, acc[3][2]);
                acc[3][3] = fma2(d3, wB.y, acc[3][3]);
            }
        }
        __syncthreads();
    }

#pragma unroll
    for (int j = 0; j < 4; j++) {
        if (vi[j] >= 0) {
            float* op = out + (size_t)vi[j] * COUT + tc * 8;
            float2 p0 = unpack2(acc[j][0]);
            float2 p1 = unpack2(acc[j][1]);
            float2 p2 = unpack2(acc[j][2]);
            float2 p3 = unpack2(acc[j][3]);
            *(float4*)(op)     = make_float4(p0.x, p0.y, p1.x, p1.y);
            *(float4*)(op + 4) = make_float4(p2.x, p2.y, p3.x, p3.y);
        }
    }
}

// ---------------- dense large-D conv (D>=16) ----------------
template <int CIN, int COUT>
__global__ void __launch_bounds__(128) k_conv(const float* __restrict__ in,
                                              const float* __restrict__ W,
                                              float* __restrict__ out,
                                              const float* __restrict__ mask,
                                              int D) {
    constexpr int KC  = (CIN % 4 == 0) ? 4 : CIN;
    constexpr int NCH = CIN / KC;
    constexpr int STR = KC + 1;
    constexpr int NCT = COUT / 32;
    constexpr int HV  = 6 * 6 * 10;

    __shared__ ull sIn[HV * STR];
    __shared__ __align__(16) float sW[27 * KC * 32];

    const int tilesX = (D + 7) >> 3;
    const int tilesY = (D + 3) >> 2;
    int bi = blockIdx.x;
    const int ct = bi % NCT;
    int tb = bi / NCT;
    const int tx = tb % tilesX; tb /= tilesX;
    const int ty = tb % tilesY;
    const int tz = tb / tilesY;
    const int z0 = tz * 4, y0 = ty * 4, x0 = tx * 8;
    const int c0 = ct * 32;

    const int tid = threadIdx.x;
    const int tc  = tid & 3;
    const int tv  = tid >> 2;
    const int vy  = tv >> 3;
    const int vx  = tv & 7;

    const float* hsrc[3];
    ull*         hdst[3];
#pragma unroll
    for (int s = 0; s < 3; s++) {
        int v = tid + s * 128;
        hsrc[s] = nullptr;
        hdst[s] = nullptr;
        if (v < HV) {
            int lz = v / 60, r = v - lz * 60;
            int ly = r / 10, lx = r - ly * 10;
            int gz = z0 - 1 + lz, gy = y0 - 1 + ly, gx = x0 - 1 + lx;
            hdst[s] = &sIn[v * STR];
            if ((unsigned)gz < (unsigned)D && (unsigned)gy < (unsigned)D &&
                (unsigned)gx < (unsigned)D)
                hsrc[s] = &in[((gz * D + gy) * D + gx) * CIN];
        }
    }

    ull acc[4][4];
#pragma unroll
    for (int i = 0; i < 4; i++)
#pragma unroll
        for (int j = 0; j < 4; j++) acc[i][j] = 0ull;

#pragma unroll 1
    for (int ch = 0; ch < NCH; ch++) {
        const int ck = ch * KC;
        if (KC == 4) {
#pragma unroll
            for (int s = 0; s < 3; s++) {
                if (hdst[s]) {
                    float4 val = make_float4(0.f, 0.f, 0.f, 0.f);
                    if (hsrc[s]) val = *(const float4*)(hsrc[s] + ck);
                    ull* sp = hdst[s];
                    sp[0] = dup2(val.x);
                    sp[1] = dup2(val.y);
                    sp[2] = dup2(val.z);
                    sp[3] = dup2(val.w);
                }
            }
        } else {
            for (int i = tid; i < HV * KC; i += 128) {
                int v = i / KC, k = i - v * KC;
                int lz = v / 60, r = v - lz * 60;
                int ly = r / 10, lx = r - ly * 10;
                int gz = z0 - 1 + lz, gy = y0 - 1 + ly, gx = x0 - 1 + lx;
                float val = 0.f;
                if ((unsigned)gz < (unsigned)D && (unsigned)gy < (unsigned)D &&
                    (unsigned)gx < (unsigned)D)
                    val = in[((gz * D + gy) * D + gx) * CIN + ck + k];
                sIn[v * STR + k] = dup2(val);
            }
        }
        for (int i = tid; i < 27 * KC * 8; i += 128) {
            int row = i >> 3, c4 = i & 7;
            int t = row / KC, k = row - t * KC;
            *(float4*)&sW[row * 32 + c4 * 4] =
                *(const float4*)&W[(t * CIN + ck + k) * COUT + c0 + c4 * 4];
        }
        __syncthreads();

#pragma unroll 1
        for (int dz = 0; dz < 3; ++dz)
#pragma unroll
            for (int dy = 0; dy < 3; ++dy) {
                const int vb = dz * 60 + (vy + dy) * 10 + vx;
                const float* wrow = &sW[(dz * 3 + dy) * 3 * KC * 32 + (tc << 3)];
#pragma unroll
                for (int dx = 0; dx < 3; ++dx) {
                    const ull* ip = &sIn[(vb + dx) * STR];
                    const float* wp = wrow + dx * KC * 32;
#pragma unroll
                    for (int k = 0; k < KC; ++k) {
                        ulonglong2 wA = *(const ulonglong2*)(wp + k * 32);
                        ulonglong2 wB = *(const ulonglong2*)(wp + k * 32 + 4);
#pragma unroll
                        for (int vz = 0; vz < 4; ++vz) {
                            ull a = ip[vz * (60 * STR) + k];
                            acc[vz][0] = fma2(a, wA.x, acc[vz][0]);
                            acc[vz][1] = fma2(a, wA.y, acc[vz][1]);
                            acc[vz][2] = fma2(a, wB.x, acc[vz][2]);
                            acc[vz][3] = fma2(a, wB.y, acc[vz][3]);
                        }
                    }
                }
            }
        __syncthreads();
    }

    const int cb = c0 + (tc << 3);
    const int gy = y0 + vy, gx = x0 + vx;
    if (gy < D && gx < D) {
#pragma unroll
        for (int vz = 0; vz < 4; ++vz) {
            int gz = z0 + vz;
            if (gz < D) {
                int vox = (gz * D + gy) * D + gx;
                float m = mask[vox];
                float4 o0, o1;
                if (m > 0.f) {
                    float2 p0 = unpack2(acc[vz][0]);
                    float2 p1 = unpack2(acc[vz][1]);
                    float2 p2 = unpack2(acc[vz][2]);
                    float2 p3 = unpack2(acc[vz][3]);
                    o0 = make_float4(p0.x, p0.y, p1.x, p1.y);
                    o1 = make_float4(p2.x, p2.y, p3.x, p3.y);
                } else {
                    o0 = make_float4(0.f, 0.f, 0.f, 0.f);
                    o1 = make_float4(0.f, 0.f, 0.f, 0.f);
                }
                float* op = out + (size_t)vox * COUT + cb;
                *(float4*)(op)     = o0;
                *(float4*)(op + 4) = o1;
            }
        }
    }
}

// ---------------- small-D conv (D<=8) ----------------
template <int CIN, int COUT>
__global__ void __launch_bounds__(256) k_conv_small(const float* __restrict__ in,
                                                    const float* __restrict__ W,
                                                    float* __restrict__ out,
                                                    const float* __restrict__ mask,
                                                    int D) {
    __shared__ __align__(16) float sIn[27 * CIN];

    const int vox = blockIdx.x;
    const int x = vox % D;
    const int t0 = vox / D;
    const int y = t0 % D;
    const int z = t0 / D;
    const int c = threadIdx.x;

    const int dz0 = (z > 0) ? 0 : 1, dz1 = (z < D - 1) ? 2 : 1;
    const int dy0 = (y > 0) ? 0 : 1, dy1 = (y < D - 1) ? 2 : 1;
    const int dx0 = (x > 0) ? 0 : 1, dx1 = (x < D - 1) ? 2 : 1;

    const int nz = dz1 - dz0 + 1, ny = dy1 - dy0 + 1, nx = dx1 - dx0 + 1;
    const int nv = nz * ny * nx;
    for (int i = c; i < nv * CIN; i += COUT) {
        int v = i / CIN, k = i - v * CIN;
        int lz = v / (ny * nx), r = v - lz * (ny * nx);
        int ly = r / nx, lx = r - ly * nx;
        int dz = dz0 + lz, dy = dy0 + ly, dx = dx0 + lx;
        int gz = z + dz - 1, gy = y + dy - 1, gx = x + dx - 1;
        sIn[((dz * 3 + dy) * 3 + dx) * CIN + k] =
            in[((gz * D + gy) * D + gx) * CIN + k];
    }
    __syncthreads();

    float a0 = 0.f, a1 = 0.f, a2 = 0.f, a3 = 0.f;
#pragma unroll 1
    for (int dz = dz0; dz <= dz1; ++dz)
#pragma unroll 1
        for (int dy = dy0; dy <= dy1; ++dy)
#pragma unroll 1
            for (int dx = dx0; dx <= dx1; ++dx) {
                const int tap = (dz * 3 + dy) * 3 + dx;
                const float* ip = &sIn[tap * CIN];
                const float* wp = &W[tap * CIN * COUT + c];
#pragma unroll 4
                for (int k = 0; k < CIN; k += 4) {
                    float4 a = *(const float4*)(ip + k);
                    a0 = fmaf(a.x, wp[(k + 0) * COUT], a0);
                    a1 = fmaf(a.y, wp[(k + 1) * COUT], a1);
                    a2 = fmaf(a.z, wp[(k + 2) * COUT], a2);
                    a3 = fmaf(a.w, wp[(k + 3) * COUT], a3);
                }
            }
    float acc = (a0 + a1) + (a2 + a3);

    float m = mask[vox];
    out[(size_t)vox * COUT + c] = (m > 0.f) ? acc : 0.f;
}

// ---------------- masked 2x2x2 max-pool (float4 per thread) ----------------
__global__ void k_pool(const float* __restrict__ in, float* __restrict__ out,
                       const float* __restrict__ mIn, float* __restrict__ mOut,
                       int Do, int C) {
    int vo = blockIdx.x;
    int c4 = threadIdx.x;
    int xo = vo % Do; int t = vo / Do;
    int yo = t % Do;  int zo = t / Do;
    int D  = Do * 2;
    const float4* in4 = (const float4*)in;
    const int C4 = C >> 2;

    float m = 0.f;
    float4 val = make_float4(-3.402823466e+38f, -3.402823466e+38f,
                             -3.402823466e+38f, -3.402823466e+38f);
#pragma unroll
    for (int a = 0; a < 2; a++)
#pragma unroll
        for (int b = 0; b < 2; b++)
#pragma unroll
            for (int e = 0; e < 2; e++) {
                int vi = ((zo * 2 + a) * D + (yo * 2 + b)) * D + (xo * 2 + e);
                if (mIn[vi] > 0.f) {
                    m = 1.f;
                    float4 v = in4[(size_t)vi * C4 + c4];
                    val.x = fmaxf(val.x, v.x);
                    val.y = fmaxf(val.y, v.y);
                    val.z = fmaxf(val.z, v.z);
                    val.w = fmaxf(val.w, v.w);
                }
            }
    float4 o = (m > 0.f) ? val : make_float4(0.f, 0.f, 0.f, 0.f);
    ((float4*)out)[(size_t)vo * C4 + c4] = o;
    if (c4 == 0) mOut[vo] = m;
}

// ---------------- launch ----------------
static inline int convgrid(int D, int cout) {
    int tx = (D + 7) / 8;
    int ty = (D + 3) / 4;
    return tx * ty * ty * (cout / 32);
}

extern "C" void kernel_launch(void* const* d_in, const int* in_sizes, int n_in,
                              void* d_out, int out_size) {
    const float* feats = (const float*)d_in[0];
    const int*   coors = (const int*)d_in[1];
    const float* Wp[14];
    for (int i = 0; i < 14; i++) Wp[i] = (const float*)d_in[2 + i];
    const int N = in_sizes[0] / 3;

    float *bufA, *bufB, *maskBase, *pad;
    cudaGetSymbolAddress((void**)&bufA, g_bufA);
    cudaGetSymbolAddress((void**)&bufB, g_bufB);
    cudaGetSymbolAddress((void**)&maskBase, g_mask);
    cudaGetSymbolAddress((void**)&pad, g_pad);
    const int moff[7] = {0, 262144, 294912, 299008, 299520, 299584, 299592};
    float* mk[7];
    for (int i = 0; i < 7; i++) mk[i] = maskBase + moff[i];

    k_init<<<NVOX / 256, 256>>>();
    k_scatter_max<<<(N + 255) / 256, 256>>>(coors, N);
    k_scatter_write<<<NVOX / 256, 256>>>(feats);
    k_compact<<<NVOX / 256, 256>>>();
    k_zero<<<(PDIM * PDIM * PDIM * 16 + 255) / 256, 256>>>();

    // block 0 @ 64^3: dense conv0, sparse repack to padded, gather conv1.
    // nocc <= N, so (N+63)/64 blocks cover the whole compacted list.
    k_conv<3, 64><<<convgrid(64, 64), 128>>>(bufA, Wp[0], bufB, mk[0], 64);
    k_repack<<<NVOX * 16 / 256, 256>>>();
    k_gconv<<<(N + 63) / 64, 128>>>(pad, Wp[1], bufA);
    k_pool<<<32 * 32 * 32, 64 / 4>>>(bufA, bufB, mk[0], mk[1], 32, 64);
    // block 1 @ 32^3
    k_conv<64, 96><<<convgrid(32, 96), 128>>>(bufB, Wp[2], bufA, mk[1], 32);
    k_conv<96, 96><<<convgrid(32, 96), 128>>>(bufA, Wp[3], bufB, mk[1], 32);
    k_pool<<<16 * 16 * 16, 96 / 4>>>(bufB, bufA, mk[1], mk[2], 16, 96);
    // block 2 @ 16^3
    k_conv<96, 128><<<convgrid(16, 128), 128>>>(bufA, Wp[4], bufB, mk[2], 16);
    k_conv<128, 128><<<convgrid(16, 128), 128>>>(bufB, Wp[5], bufA, mk[2], 16);
    k_pool<<<8 * 8 * 8, 128 / 4>>>(bufA, bufB, mk[2], mk[3], 8, 128);
    // block 3 @ 8^3
    k_conv_small<128, 160><<<512, 160>>>(bufB, Wp[6], bufA, mk[3], 8);
    k_conv_small<160, 160><<<512, 160>>>(bufA, Wp[7], bufB, mk[3], 8);
    k_pool<<<4 * 4 * 4, 160 / 4>>>(bufB, bufA, mk[3], mk[4], 4, 160);
    // block 4 @ 4^3
    k_conv_small<160, 192><<<64, 192>>>(bufA, Wp[8], bufB, mk[4], 4);
    k_conv_small<192, 192><<<64, 192>>>(bufB, Wp[9], bufA, mk[4], 4);
    k_pool<<<2 * 2 * 2, 192 / 4>>>(bufA, bufB, mk[4], mk[5], 2, 192);
    // block 5 @ 2^3
    k_conv_small<192, 224><<<8, 224>>>(bufB, Wp[10], bufA, mk[5], 2);
    k_conv_small<224, 224><<<8, 224>>>(bufA, Wp[11], bufB, mk[5], 2);
    k_pool<<<1, 224 / 4>>>(bufB, bufA, mk[5], mk[6], 1, 224);
    // block 6 @ 1^3 -> final output (1,1,1,1,256)
    k_conv_small<224, 256><<<1, 256>>>(bufA, Wp[12], bufB, mk[6], 1);
    k_conv_small<256, 256><<<1, 256>>>(bufB, Wp[13], (float*)d_out, mk[6], 1);
}